// round 15
// baseline (speedup 1.0000x reference)
#include <cuda_runtime.h>
#include <cuda_bf16.h>
#include <math.h>

// Problem constants
#define EMB   1024
#define HID   1024
#define SEQ   128
#define BATCH 64
#define VOCAB 10000
#define VPAD  10112              // 79 * 128
#define BH    (BATCH * HID)      // 65536
#define ROWS  (SEQ * BATCH)      // 8192

// h layout: [slot][16 chunks][8KB swizzled (64 rows x 128B)]
#define H_SLOT_BYTES  131072
#define H_CHUNK_BYTES 8192
// tile layout (B/X/W): [128-row tile][16 chunks][16KB swizzled]
#define T_TILE_BYTES  262144
#define T_CHUNK_BYTES 16384

// Fused persistent kernel config
#define NB_L0 32
#define NBLK  96                 // 32 L0 + 64 L1
#define NGRID 148
#define NTHR  544                // 16 compute warps + 1 producer warp
#define PTID  512                // producer thread
#define NT_N  79
#define NTILES (64 * NT_N)       // 5056 logits tiles
#define NXT   512                // 64 x 8 xproj tiles (served first)
#define A_BASE 131072            // recur A stages after weights
#define L0_STAGE 16384
#define L1_STAGE 32768
#define RECUR_SMEM (131072 + 3 * 32768)   // 229376

// 128x128 GEMM config
#define NKT  16
#define OP_BYTES 16384
#define STAGE_BYTES (4 * OP_BYTES)

typedef unsigned long long ull;

// ---------------- scratch (device globals) ----------------------------------
__device__ float g_xproj0[ROWS * HID];
__device__ unsigned g_bar;
__device__ unsigned g_tileq;
__device__ unsigned g_xp[64];    // per-mt xproj tile completion counters
__device__ __nv_bfloat16 g_h0h[(SEQ + 1) * BH];
__device__ __nv_bfloat16 g_h0l[(SEQ + 1) * BH];
__device__ __nv_bfloat16 g_h1h[(SEQ + 1) * BH];
__device__ __nv_bfloat16 g_h1l[(SEQ + 1) * BH];
__device__ __nv_bfloat16 g_Bh[VPAD * HID];
__device__ __nv_bfloat16 g_Bl[VPAD * HID];
__device__ __nv_bfloat16 g_Wh[HID * HID];
__device__ __nv_bfloat16 g_Wl[HID * HID];
__device__ __nv_bfloat16 g_Xh[ROWS * HID];
__device__ __nv_bfloat16 g_Xl[ROWS * HID];

// ---------------- helpers -----------------------------------------------------
__device__ __forceinline__ unsigned smem_u32(const void* p) {
    unsigned a;
    asm("{ .reg .u64 t; cvta.to.shared.u64 t, %1; cvt.u32.u64 %0, t; }"
        : "=r"(a) : "l"(p));
    return a;
}

#define SWZ(o) ((o) ^ (((o) >> 3) & 0x70))

__device__ __forceinline__ unsigned hoff_bytes(int slot, int m, int k) {
    unsigned o = (unsigned)(m * 128 + (k & 63) * 2);
    return (unsigned)(slot * H_SLOT_BYTES + ((k >> 6) * H_CHUNK_BYTES)) + SWZ(o);
}

#define MBAR_INIT(addr, cnt) \
    asm volatile("mbarrier.init.shared.b64 [%0], %1;" \
                 :: "r"((unsigned)(addr)), "r"((unsigned)(cnt)) : "memory")
#define MBAR_EXPECT_TX(addr, tx) \
    asm volatile("mbarrier.arrive.expect_tx.shared.b64 _, [%0], %1;" \
                 :: "r"((unsigned)(addr)), "r"((unsigned)(tx)) : "memory")
#define MBAR_ARRIVE(addr) \
    asm volatile("mbarrier.arrive.shared.b64 _, [%0];" \
                 :: "r"((unsigned)(addr)) : "memory")
#define BAR_SYNC(id, n) \
    asm volatile("bar.sync %0, %1;" :: "r"(id), "r"(n) : "memory")

#define MBARRIER_WAIT_PARITY(addr, par) do {                                  \
    unsigned _m = (unsigned)(addr), _p = (unsigned)(par), _d;                 \
    asm volatile("{\n\t.reg .pred p;\n\t"                                     \
        "mbarrier.try_wait.parity.acquire.cta.shared::cta.b64 p, [%1], %2;\n\t" \
        "selp.b32 %0, 1, 0, p;\n\t}"                                          \
        : "=r"(_d) : "r"(_m), "r"(_p) : "memory");                            \
    if (!_d) {                                                                \
        asm volatile("{\n\t.reg .pred P1;\n\t"                                \
            "WL_%=:\n\t"                                                      \
            "mbarrier.try_wait.parity.acquire.cta.shared::cta.b64 P1, [%0], %1, 0x989680;\n\t" \
            "@P1 bra.uni WD_%=;\n\t"                                          \
            "bra.uni WL_%=;\n\t"                                              \
            "WD_%=:\n\t}" :: "r"(_m), "r"(_p) : "memory");                    \
    }                                                                         \
} while (0)

__device__ __forceinline__ void bulk_g2s(unsigned dst, const void* src,
                                         unsigned bytes, unsigned mbar) {
    asm volatile(
        "cp.async.bulk.shared::cluster.global.mbarrier::complete_tx::bytes "
        "[%0], [%1], %2, [%3];"
        :: "r"(dst), "l"(src), "r"(bytes), "r"(mbar) : "memory");
}

__device__ __forceinline__ unsigned ld_acq(const unsigned* p) {
    unsigned v;
    asm volatile("ld.global.acquire.gpu.b32 %0, [%1];" : "=r"(v) : "l"(p) : "memory");
    return v;
}
__device__ __forceinline__ void red_rel(unsigned* p, unsigned v) {
    asm volatile("red.release.gpu.global.add.u32 [%0], %1;" :: "l"(p), "r"(v) : "memory");
}

__device__ __forceinline__ void ldsm4(unsigned* r, unsigned addr) {
    asm volatile("ldmatrix.sync.aligned.m8n8.x4.shared.b16 {%0,%1,%2,%3}, [%4];"
                 : "=r"(r[0]), "=r"(r[1]), "=r"(r[2]), "=r"(r[3]) : "r"(addr));
}
__device__ __forceinline__ void mma16816(float* c, const unsigned* a,
                                         unsigned b0, unsigned b1) {
    asm volatile(
        "mma.sync.aligned.m16n8k16.row.col.f32.bf16.bf16.f32 "
        "{%0,%1,%2,%3}, {%4,%5,%6,%7}, {%8,%9}, {%0,%1,%2,%3};"
        : "+f"(c[0]), "+f"(c[1]), "+f"(c[2]), "+f"(c[3])
        : "r"(a[0]), "r"(a[1]), "r"(a[2]), "r"(a[3]), "r"(b0), "r"(b1));
}

__device__ __forceinline__ void split_bf16(float v, __nv_bfloat16& h,
                                           __nv_bfloat16& l) {
    h = __float2bfloat16(v);
    l = __float2bfloat16(v - __bfloat162float(h));
}

// ---------------- init ----------------------------------------------------------
__global__ void init_kernel(const float* __restrict__ hidden) {
    int i = blockIdx.x * blockDim.x + threadIdx.x;
    if (i == 0) { g_bar = 0; g_tileq = 0; }
    if (i < 64) g_xp[i] = 0;
    if (i < BH) {
        int b = i >> 10, n = i & 1023;
        unsigned off = hoff_bytes(0, b, n);
        __nv_bfloat16 h, l;
        split_bf16(hidden[i], h, l);
        *(__nv_bfloat16*)((char*)g_h0h + off) = h;
        *(__nv_bfloat16*)((char*)g_h0l + off) = l;
        split_bf16(hidden[BH + i], h, l);
        *(__nv_bfloat16*)((char*)g_h1h + off) = h;
        *(__nv_bfloat16*)((char*)g_h1l + off) = l;
    }
}

// ---------------- convert fp32 rows -> split bf16 tiles (swizzled) -------------
__global__ __launch_bounds__(256) void conv_tiles_kernel(
    const float* __restrict__ src, const int* __restrict__ idx,
    __nv_bfloat16* __restrict__ dh, __nv_bfloat16* __restrict__ dl, int total4)
{
    int i = blockIdx.x * 256 + threadIdx.x;
    if (i >= total4) return;
    int e = i * 4;
    int r = e >> 10, k = e & 1023;
    int srow = idx ? idx[r] : r;
    float4 a = *(const float4*)(src + (size_t)srow * 1024 + k);
    __nv_bfloat16 h0, l0, h1, l1, h2, l2, h3, l3;
    split_bf16(a.x, h0, l0); split_bf16(a.y, h1, l1);
    split_bf16(a.z, h2, l2); split_bf16(a.w, h3, l3);
    unsigned o = (unsigned)((r & 127) * 128 + (k & 63) * 2);
    unsigned off = (unsigned)((r >> 7) * T_TILE_BYTES + (k >> 6) * T_CHUNK_BYTES)
                 + SWZ(o);
    *(__nv_bfloat162*)((char*)dh + off)     = __nv_bfloat162(h0, h1);
    *(__nv_bfloat162*)((char*)dh + off + 4) = __nv_bfloat162(h2, h3);
    *(__nv_bfloat162*)((char*)dl + off)     = __nv_bfloat162(l0, l1);
    *(__nv_bfloat162*)((char*)dl + off + 4) = __nv_bfloat162(l2, l3);
}

// ---------------- recur: layer-0 step (16 warps, ks-split inside chunk) --------
__device__ __forceinline__ void step_l0(char* smc, unsigned sb, unsigned mbf,
                                        unsigned mbe, int bid, int k, int u0,
                                        int tid, int lane, int wid)
{
    const char* a0h = (const char*)g_h0h + (size_t)k * H_SLOT_BYTES;
    const char* a0l = (const char*)g_h0l + (size_t)k * H_SLOT_BYTES;

    if (tid == PTID) {
        #pragma unroll 1
        for (int c = 0; c < 16; c++) {
            int uu = u0 + c, s = uu & 3, q = uu >> 2;
            if (uu >= 4) MBARRIER_WAIT_PARITY(mbe + s * 8, (q - 1) & 1);
            unsigned dst = sb + A_BASE + s * L0_STAGE;
            MBAR_EXPECT_TX(mbf + s * 8, 16384u);
            bulk_g2s(dst,        a0h + c * H_CHUNK_BYTES, 8192, mbf + s * 8);
            bulk_g2s(dst + 8192, a0l + c * H_CHUNK_BYTES, 8192, mbf + s * 8);
        }
    } else if (wid < 16) {
        const int ksh = wid >> 3;            // ks-half: 0 -> ks 0,1 ; 1 -> ks 2,3
        const int w7 = wid & 7;
        const int wm = w7 >> 1, wn = w7 & 1;
        const unsigned xm    = (unsigned)((lane & 7) << 4);
        const unsigned aoffA = (unsigned)((wm * 16 + (lane & 7) + ((lane >> 3) & 1) * 8) * 128);
        const unsigned kbA   = (unsigned)((lane >> 4) * 16);
        const unsigned boffB = (unsigned)((wn * 16 + (lane & 7) + ((lane >> 4) << 3)) * 128);
        const unsigned kbB   = (unsigned)(((lane >> 3) & 1) * 16);

        float acc[2][4] = {};

        #pragma unroll 1
        for (int c = 0; c < 16; c++) {
            int uu = u0 + c, s = uu & 3, q = uu >> 2;
            MBARRIER_WAIT_PARITY(mbf + s * 8, q & 1);
            unsigned stg = sb + A_BASE + s * L0_STAGE;
            unsigned wbh = sb + (unsigned)(c * 4096);
            unsigned wbl = wbh + 65536;
            #pragma unroll
            for (int ks = ksh * 2; ks < ksh * 2 + 2; ks++) {
                unsigned kA = ((unsigned)(ks * 32) + kbA) ^ xm;
                unsigned kB = ((unsigned)(ks * 32) + kbB) ^ xm;
                unsigned ah[4], al[4], bh[4], bl[4];
                ldsm4(ah, stg + aoffA + kA);
                ldsm4(al, stg + 8192 + aoffA + kA);
                ldsm4(bh, wbh + boffB + kB);
                ldsm4(bl, wbl + boffB + kB);
                mma16816(acc[0], ah, bh[0], bh[1]);
                mma16816(acc[0], al, bh[0], bh[1]);
                mma16816(acc[0], ah, bl[0], bl[1]);
                mma16816(acc[1], ah, bh[2], bh[3]);
                mma16816(acc[1], al, bh[2], bh[3]);
                mma16816(acc[1], ah, bl[2], bl[3]);
            }
            if (lane == 0) MBAR_ARRIVE(mbe + s * 8);
        }

        // reduce ks-halves in retired stage, epilogue by ksh 0
        float* red = (float*)(smc + A_BASE + ((u0 + 15) & 3) * L0_STAGE);
        int r = lane >> 2, c0 = 2 * (lane & 3);
        int mrow = wm * 16 + r;
        BAR_SYNC(1, 512);
        if (ksh == 1) {
            #pragma unroll
            for (int n2 = 0; n2 < 2; n2++) {
                int col = wn * 16 + n2 * 8 + c0;
                *(float2*)&red[mrow * 32 + col]       = make_float2(acc[n2][0], acc[n2][1]);
                *(float2*)&red[(mrow + 8) * 32 + col] = make_float2(acc[n2][2], acc[n2][3]);
            }
        }
        BAR_SYNC(1, 512);
        if (ksh == 0) {
            int mt = k >> 1;
            while (ld_acq(&g_xp[mt]) < 8u) { }
            #pragma unroll
            for (int n2 = 0; n2 < 2; n2++) {
                int col = wn * 16 + n2 * 8 + c0;
                int gn = bid * 32 + col;
                float2 r0 = *(const float2*)&red[mrow * 32 + col];
                float2 r1 = *(const float2*)&red[(mrow + 8) * 32 + col];
                const float* xp0 = g_xproj0 + ((size_t)k * BATCH + mrow) * HID + gn;
                const float* xp1 = g_xproj0 + ((size_t)k * BATCH + mrow + 8) * HID + gn;
                float2 x0 = *(const float2*)xp0;
                float2 x1 = *(const float2*)xp1;
                float t0 = tanhf(acc[n2][0] + r0.x + x0.x);
                float t1 = tanhf(acc[n2][1] + r0.y + x0.y);
                float t2 = tanhf(acc[n2][2] + r1.x + x1.x);
                float t3 = tanhf(acc[n2][3] + r1.y + x1.y);
                __nv_bfloat16 h0, l0, h1, l1, h2, l2, h3, l3;
                split_bf16(t0, h0, l0); split_bf16(t1, h1, l1);
                split_bf16(t2, h2, l2); split_bf16(t3, h3, l3);
                unsigned o0 = hoff_bytes(k + 1, mrow, gn);
                unsigned o1 = hoff_bytes(k + 1, mrow + 8, gn);
                *(__nv_bfloat162*)((char*)g_h0h + o0) = __nv_bfloat162(h0, h1);
                *(__nv_bfloat162*)((char*)g_h0l + o0) = __nv_bfloat162(l0, l1);
                *(__nv_bfloat162*)((char*)g_h0h + o1) = __nv_bfloat162(h2, h3);
                *(__nv_bfloat162*)((char*)g_h0l + o1) = __nv_bfloat162(l2, l3);
            }
        }
    }
}

// ---------------- recur: layer-1 step (16 warps: wm x kq x ks-half) ------------
__device__ __forceinline__ void step_l1(char* smc, unsigned sb, unsigned mbf,
                                        unsigned mbe, int bid, int k, int u0,
                                        int tid, int lane, int wid,
                                        const float* __restrict__ bh1)
{
    const char* a0h = (const char*)g_h0h + (size_t)k * H_SLOT_BYTES;
    const char* a0l = (const char*)g_h0l + (size_t)k * H_SLOT_BYTES;
    const char* a1h = (const char*)g_h1h + (size_t)(k - 1) * H_SLOT_BYTES;
    const char* a1l = (const char*)g_h1l + (size_t)(k - 1) * H_SLOT_BYTES;

    if (tid == PTID) {
        #pragma unroll 1
        for (int c = 0; c < 16; c++) {
            int uu = u0 + c, s = uu % 3, q = uu / 3;
            if (uu >= 3) MBARRIER_WAIT_PARITY(mbe + s * 8, (q - 1) & 1);
            unsigned dst = sb + A_BASE + s * L1_STAGE;
            MBAR_EXPECT_TX(mbf + s * 8, 32768u);
            bulk_g2s(dst,         a0h + c * H_CHUNK_BYTES, 8192, mbf + s * 8);
            bulk_g2s(dst + 8192,  a0l + c * H_CHUNK_BYTES, 8192, mbf + s * 8);
            bulk_g2s(dst + 16384, a1h + c * H_CHUNK_BYTES, 8192, mbf + s * 8);
            bulk_g2s(dst + 24576, a1l + c * H_CHUNK_BYTES, 8192, mbf + s * 8);
        }
    } else if (wid < 16) {
        const int ksh = wid >> 3;
        const int w7 = wid & 7;
        const int wm = w7 >> 1, kq = w7 & 1;
        const unsigned xm    = (unsigned)((lane & 7) << 4);
        const unsigned aoffA = (unsigned)((wm * 16 + (lane & 7) + ((lane >> 3) & 1) * 8) * 128);
        const unsigned kbA   = (unsigned)((lane >> 4) * 16);
        const unsigned boffB = (unsigned)(((lane & 7) + ((lane >> 4) << 3)) * 128);
        const unsigned kbB   = (unsigned)(((lane >> 3) & 1) * 16);
        const unsigned aq    = (unsigned)(kq * 16384);

        float acc[2][4] = {};

        #pragma unroll 1
        for (int c = 0; c < 16; c++) {
            int uu = u0 + c, s = uu % 3, q = uu / 3;
            MBARRIER_WAIT_PARITY(mbf + s * 8, q & 1);
            unsigned stg = sb + A_BASE + s * L1_STAGE + aq;
            unsigned wbh = sb + (unsigned)(kq * 65536 + c * 2048);
            unsigned wbl = wbh + 32768;
            #pragma unroll
            for (int ks = ksh * 2; ks < ksh * 2 + 2; ks++) {
                unsigned kA = ((unsigned)(ks * 32) + kbA) ^ xm;
                unsigned kB = ((unsigned)(ks * 32) + kbB) ^ xm;
                unsigned ah[4], al[4], bh[4], bl[4];
                ldsm4(ah, stg + aoffA + kA);
                ldsm4(al, stg + 8192 + aoffA + kA);
                ldsm4(bh, wbh + boffB + kB);
                ldsm4(bl, wbl + boffB + kB);
                mma16816(acc[0], ah, bh[0], bh[1]);
                mma16816(acc[0], al, bh[0], bh[1]);
                mma16816(acc[0], ah, bl[0], bl[1]);
                mma16816(acc[1], ah, bh[2], bh[3]);
                mma16816(acc[1], al, bh[2], bh[3]);
                mma16816(acc[1], ah, bl[2], bl[3]);
            }
            if (lane == 0) MBAR_ARRIVE(mbe + s * 8);
        }

        // combine 4 partial groups (kq x ksh) in a retired stage
        float* red = (float*)(smc + A_BASE + ((u0 + 15) % 3) * L1_STAGE);
        int r = lane >> 2, c0 = 2 * (lane & 3);
        int mrow = wm * 16 + r;
        int g = kq * 2 + ksh;
        BAR_SYNC(1, 512);
        if (g != 0) {
            float* pr = red + (g - 1) * 1024;
            #pragma unroll
            for (int n2 = 0; n2 < 2; n2++) {
                int col = n2 * 8 + c0;
                *(float2*)&pr[mrow * 16 + col]       = make_float2(acc[n2][0], acc[n2][1]);
                *(float2*)&pr[(mrow + 8) * 16 + col] = make_float2(acc[n2][2], acc[n2][3]);
            }
        }
        BAR_SYNC(1, 512);
        if (g == 0) {
            int gnb = (bid - NB_L0) * 16;
            #pragma unroll
            for (int n2 = 0; n2 < 2; n2++) {
                int col = n2 * 8 + c0;
                int gn = gnb + col;
                float2 p00 = *(const float2*)&red[0 * 1024 + mrow * 16 + col];
                float2 p01 = *(const float2*)&red[1 * 1024 + mrow * 16 + col];
                float2 p02 = *(const float2*)&red[2 * 1024 + mrow * 16 + col];
                float2 p10 = *(const float2*)&red[0 * 1024 + (mrow + 8) * 16 + col];
                float2 p11 = *(const float2*)&red[1 * 1024 + (mrow + 8) * 16 + col];
                float2 p12 = *(const float2*)&red[2 * 1024 + (mrow + 8) * 16 + col];
                float2 bv = *(const float2*)(bh1 + gn);
                float t0 = tanhf(acc[n2][0] + p00.x + p01.x + p02.x + bv.x);
                float t1 = tanhf(acc[n2][1] + p00.y + p01.y + p02.y + bv.y);
                float t2 = tanhf(acc[n2][2] + p10.x + p11.x + p12.x + bv.x);
                float t3 = tanhf(acc[n2][3] + p10.y + p11.y + p12.y + bv.y);
                __nv_bfloat16 h0, l0, h1, l1, h2, l2, h3, l3;
                split_bf16(t0, h0, l0); split_bf16(t1, h1, l1);
                split_bf16(t2, h2, l2); split_bf16(t3, h3, l3);
                unsigned o0 = hoff_bytes(k, mrow, gn);
                unsigned o1 = hoff_bytes(k, mrow + 8, gn);
                *(__nv_bfloat162*)((char*)g_h1h + o0) = __nv_bfloat162(h0, h1);
                *(__nv_bfloat162*)((char*)g_h1l + o0) = __nv_bfloat162(l0, l1);
                *(__nv_bfloat162*)((char*)g_h1h + o1) = __nv_bfloat162(h2, h3);
                *(__nv_bfloat162*)((char*)g_h1l + o1) = __nv_bfloat162(l2, l3);
            }
        }
    }
}

// ---------------- shared 128x128 GEMM machinery (16 warps, 32m x 32n each) -----
template<bool FOURTH>
__device__ __forceinline__ void compute_chunk128(
    unsigned st, const unsigned* aoffA, const unsigned* aoffB,
    unsigned kbA, unsigned kbB, unsigned xm, float acc[2][4][4])
{
    #pragma unroll
    for (int ks = 0; ks < 4; ks++) {
        unsigned kA = ((unsigned)(ks * 32) + kbA) ^ xm;
        unsigned kB = ((unsigned)(ks * 32) + kbB) ^ xm;
        unsigned ah[2][4], al[2][4], bh[2][4], bl[2][4];
        #pragma unroll
        for (int mt = 0; mt < 2; mt++) {
            ldsm4(ah[mt], st + 0 * OP_BYTES + aoffA[mt] + kA);
            ldsm4(al[mt], st + 1 * OP_BYTES + aoffA[mt] + kA);
        }
        #pragma unroll
        for (int nt = 0; nt < 2; nt++) {
            ldsm4(bh[nt], st + 2 * OP_BYTES + aoffB[nt] + kB);
            ldsm4(bl[nt], st + 3 * OP_BYTES + aoffB[nt] + kB);
        }
        #pragma unroll
        for (int mt = 0; mt < 2; mt++) {
            #pragma unroll
            for (int n2 = 0; n2 < 2; n2++) {
                mma16816(acc[mt][n2 * 2],     ah[mt], bh[n2][0], bh[n2][1]);
                mma16816(acc[mt][n2 * 2],     al[mt], bh[n2][0], bh[n2][1]);
                mma16816(acc[mt][n2 * 2],     ah[mt], bl[n2][0], bl[n2][1]);
                if (FOURTH)
                    mma16816(acc[mt][n2 * 2], al[mt], bl[n2][0], bl[n2][1]);
                mma16816(acc[mt][n2 * 2 + 1], ah[mt], bh[n2][2], bh[n2][3]);
                mma16816(acc[mt][n2 * 2 + 1], al[mt], bh[n2][2], bh[n2][3]);
                mma16816(acc[mt][n2 * 2 + 1], ah[mt], bl[n2][2], bl[n2][3]);
                if (FOURTH)
                    mma16816(acc[mt][n2 * 2 + 1], al[mt], bl[n2][2], bl[n2][3]);
            }
        }
    }
}

__device__ __forceinline__ void tile_geometry(int lane, int wid,
                                              unsigned* aoffA, unsigned* aoffB,
                                              unsigned& kbA, unsigned& kbB,
                                              unsigned& xm)
{
    const int warp_m = (wid >> 2) * 32;
    const int warp_n = (wid & 3) * 32;
    xm  = (unsigned)((lane & 7) << 4);
    const int rowA = (lane & 7) + ((lane >> 3) & 1) * 8;
    kbA = (unsigned)((lane >> 4) * 16);
    const int rowB = (lane & 7) + ((lane >> 4) << 3);
    kbB = (unsigned)(((lane >> 3) & 1) * 16);
    #pragma unroll
    for (int mt = 0; mt < 2; mt++)
        aoffA[mt] = (unsigned)((warp_m + mt * 16 + rowA) * 128);
    #pragma unroll
    for (int nt = 0; nt < 2; nt++)
        aoffB[nt] = (unsigned)((warp_n + nt * 16 + rowB) * 128);
}

// ---------------- fused persistent kernel --------------------------------------
__global__ __launch_bounds__(NTHR, 1) void fused_kernel(
    const float* __restrict__ wh0, const float* __restrict__ wx1,
    const float* __restrict__ wh1, const float* __restrict__ bh0,
    const float* __restrict__ bh1, const float* __restrict__ vb,
    float* __restrict__ out)
{
    extern __shared__ char sm[];
    __shared__ ull s_full[4], s_empty[4];   // recur rings
    __shared__ ull s_lf[2], s_le[2];        // worker rings
    __shared__ int s_tile;
    const int tid = threadIdx.x;
    const int lane = tid & 31, wid = tid >> 5;
    const int bid = blockIdx.x;
    const unsigned sb = smem_u32(sm);
    const unsigned mbf = smem_u32(&s_full[0]);
    const unsigned mbe = smem_u32(&s_empty[0]);
    const unsigned mlf = smem_u32(&s_lf[0]);
    const unsigned mle = smem_u32(&s_le[0]);

    if (tid == 0) {
        #pragma unroll
        for (int s = 0; s < 4; s++) {
            MBAR_INIT(mbf + s * 8, 1);
            MBAR_INIT(mbe + s * 8, 16);     // all 16 compute warps consume
        }
        #pragma unroll
        for (int s = 0; s < 2; s++) {
            MBAR_INIT(mlf + s * 8, 1);
            MBAR_INIT(mle + s * 8, 16);
        }
    }
    __syncthreads();

    // ================= recurrence phase (blocks 0..95) =================
    if (bid < NBLK) {
        const bool is_l1 = (bid >= NB_L0);
        if (!is_l1) {
            int nb = bid * 32;
            for (int idx = tid; idx < 32 * 1024; idx += NTHR) {
                int n = idx >> 10, kk = idx & 1023;
                float w = wh0[(size_t)(nb + n) * HID + kk];
                __nv_bfloat16 h, l; split_bf16(w, h, l);
                int c = kk >> 6;
                unsigned off = SWZ((unsigned)(n * 128 + (kk & 63) * 2));
                *(__nv_bfloat16*)(sm + c * 4096 + off) = h;
                *(__nv_bfloat16*)(sm + 65536 + c * 4096 + off) = l;
            }
        } else {
            int nb = (bid - NB_L0) * 16;
            for (int idx = tid; idx < 2 * 16 * 1024; idx += NTHR) {
                int mat = idx >> 14;
                int rr = idx & 16383;
                int n = rr >> 10, kk = rr & 1023;
                const float* W = mat ? wh1 : wx1;
                float w = W[(size_t)(nb + n) * HID + kk];
                __nv_bfloat16 h, l; split_bf16(w, h, l);
                int c = kk >> 6;
                unsigned off = SWZ((unsigned)(n * 128 + (kk & 63) * 2));
                char* base = sm + mat * 65536;
                *(__nv_bfloat16*)(base + c * 2048 + off) = h;
                *(__nv_bfloat16*)(base + 32768 + c * 2048 + off) = l;
            }
        }
        __syncthreads();

        int u = 0;
        for (int k = 0; k <= SEQ; k++) {
            bool active = is_l1 ? (k >= 1) : (k < SEQ);
            if (active) {
                if (!is_l1) step_l0(sm, sb, mbf, mbe, bid, k, u, tid, lane, wid);
                else        step_l1(sm, sb, mbf, mbe, bid, k, u, tid, lane, wid, bh1);
                u += 16;
            }
            if (k < SEQ) {
                __syncthreads();
                if (tid == 0) {
                    red_rel(&g_bar, 1u);
                    unsigned target = (unsigned)(k + 1) * NBLK;
                    while (ld_acq(&g_bar) < target) { }
                }
                __syncthreads();
            }
        }
        __syncthreads();
        if (tid == 0) red_rel(&g_bar, 1u);   // publishes h1[SEQ]
    }

    // ================= tile phase: xproj (t<NXT) then logits =================
    const char* ahb = (const char*)g_h1h;
    const char* alb = (const char*)g_h1l;
    int lu = 0;
    int prev_mt = -1;

    while (true) {
        __syncthreads();
        if (tid == 0) {
            if (prev_mt >= 0) {
                red_rel(&g_xp[prev_mt], 1u);
                prev_mt = -1;
            }
            unsigned t = atomicAdd(&g_tileq, 1u);
            s_tile = (int)t;
            if (t < NXT) {
                prev_mt = (int)(t >> 3);
            } else if (t < NXT + NTILES) {
                unsigned need = (unsigned)(((t - NXT) / NT_N) * 2 + 3) * NBLK;
                while (ld_acq(&g_bar) < need) { }
            }
        }
        __syncthreads();
        int t = s_tile;
        if (t >= NXT + NTILES) break;

        if (t < NXT) {
            // -------- xproj tile: 4-product, A=gathered emb, B=wx0 --------
            int mt = t >> 3, nt = t & 7;
            int mbase = mt * 128, nbase = nt * 128;
            const char* xah = (const char*)g_Xh + (size_t)mt * T_TILE_BYTES;
            const char* xal = (const char*)g_Xl + (size_t)mt * T_TILE_BYTES;
            const char* xbh = (const char*)g_Wh + (size_t)nt * T_TILE_BYTES;
            const char* xbl = (const char*)g_Wl + (size_t)nt * T_TILE_BYTES;

            if (tid == PTID) {
                #pragma unroll 1
                for (int c = 0; c < NKT; c++) {
                    int uu = lu + c, s = uu & 1, q = uu >> 1;
                    if (uu >= 2) MBARRIER_WAIT_PARITY(mle + s * 8, (q - 1) & 1);
                    unsigned dst = sb + (unsigned)(s * STAGE_BYTES);
                    MBAR_EXPECT_TX(mlf + s * 8, 65536u);
                    bulk_g2s(dst,                xah + c * T_CHUNK_BYTES, 16384, mlf + s * 8);
                    bulk_g2s(dst + OP_BYTES,     xal + c * T_CHUNK_BYTES, 16384, mlf + s * 8);
                    bulk_g2s(dst + 2 * OP_BYTES, xbh + c * T_CHUNK_BYTES, 16384, mlf + s * 8);
                    bulk_g2s(dst + 3 * OP_BYTES, xbl + c * T_CHUNK_BYTES, 16384, mlf + s * 8);
                }
            } else if (wid < 16) {
                unsigned aoffA[2], aoffB[2], kbA, kbB, xm;
                tile_geometry(lane, wid, aoffA, aoffB, kbA, kbB, xm);
                float acc[2][4][4] = {};
                #pragma unroll 1
                for (int c = 0; c < NKT; c++) {
                    int uu = lu + c, s = uu & 1, q = uu >> 1;
                    MBARRIER_WAIT_PARITY(mlf + s * 8, q & 1);
                    compute_chunk128<true>(sb + (unsigned)(s * STAGE_BYTES),
                                           aoffA, aoffB, kbA, kbB, xm, acc);
                    if (lane == 0) MBAR_ARRIVE(mle + s * 8);
                }
                const int warp_m = (wid >> 2) * 32;
                const int warp_n = (wid & 3) * 32;
                const int r0l = lane >> 2;
                const int c0l = 2 * (lane & 3);
                #pragma unroll
                for (int nt4 = 0; nt4 < 4; nt4++) {
                    int col = nbase + warp_n + nt4 * 8 + c0l;
                    float2 bv = *(const float2*)(bh0 + col);
                    #pragma unroll
                    for (int mt4 = 0; mt4 < 2; mt4++) {
                        int row = mbase + warp_m + mt4 * 16 + r0l;
                        float* o0 = g_xproj0 + (size_t)row * HID + col;
                        float* o1 = g_xproj0 + (size_t)(row + 8) * HID + col;
                        *(float2*)o0 = make_float2(acc[mt4][nt4][0] + bv.x,
                                                   acc[mt4][nt4][1] + bv.y);
                        *(float2*)o1 = make_float2(acc[mt4][nt4][2] + bv.x,
                                                   acc[mt4][nt4][3] + bv.y);
                    }
                }
            }
        } else {
            // -------- logits tile: 3-product, A=h1 slots, B=v_w --------
            int tl = t - NXT;
            int mt = tl / NT_N, nt = tl - mt * NT_N;
            int mbase = mt * 128, nbase = nt * 128;
            int s0 = mt * 2 + 1;
            const char* bhb = (const char*)g_Bh + (size_t)nt * T_TILE_BYTES;
            const char* blb = (const char*)g_Bl + (size_t)nt * T_TILE_BYTES;

            if (tid == PTID) {
                #pragma unroll 1
                for (int c = 0; c < NKT; c++) {
                    int uu = lu + c, s = uu & 1, q = uu >> 1;
                    if (uu >= 2) MBARRIER_WAIT_PARITY(mle + s * 8, (q - 1) & 1);
                    unsigned dst = sb + (unsigned)(s * STAGE_BYTES);
                    MBAR_EXPECT_TX(mlf + s * 8, 65536u);
                    bulk_g2s(dst,                   ahb + (size_t)s0 * H_SLOT_BYTES + c * H_CHUNK_BYTES, 8192, mlf + s * 8);
                    bulk_g2s(dst + 8192,            ahb + (size_t)(s0 + 1) * H_SLOT_BYTES + c * H_CHUNK_BYTES, 8192, mlf + s * 8);
                    bulk_g2s(dst + OP_BYTES,        alb + (size_t)s0 * H_SLOT_BYTES + c * H_CHUNK_BYTES, 8192, mlf + s * 8);
                    bulk_g2s(dst + OP_BYTES + 8192, alb + (size_t)(s0 + 1) * H_SLOT_BYTES + c * H_CHUNK_BYTES, 8192, mlf + s * 8);
                    bulk_g2s(dst + 2 * OP_BYTES,    bhb + c * T_CHUNK_BYTES, 16384, mlf + s * 8);
                    bulk_g2s(dst + 3 * OP_BYTES,    blb + c * T_CHUNK_BYTES, 16384, mlf + s * 8);
                }
            } else if (wid < 16) {
                unsigned aoffA[2], aoffB[2], kbA, kbB, xm;
                tile_geometry(lane, wid, aoffA, aoffB, kbA, kbB, xm);
                float acc[2][4][4] = {};
                #pragma unroll 1
                for (int c = 0; c < NKT; c++) {
                    int uu = lu + c, s = uu & 1, q = uu >> 1;
                    MBARRIER_WAIT_PARITY(mlf + s * 8, q & 1);
                    compute_chunk128<false>(sb + (unsigned)(s * STAGE_BYTES),
                                            aoffA, aoffB, kbA, kbB, xm, acc);
                    if (lane == 0) MBAR_ARRIVE(mle + s * 8);
                }
                const int warp_m = (wid >> 2) * 32;
                const int warp_n = (wid & 3) * 32;
                const int r0l = lane >> 2;
                const int c0l = 2 * (lane & 3);
                #pragma unroll
                for (int nt4 = 0; nt4 < 4; nt4++) {
                    int col = nbase + warp_n + nt4 * 8 + c0l;
                    if (col >= VOCAB) continue;
                    float bv0 = vb[col], bv1 = vb[col + 1];
                    #pragma unroll
                    for (int mt4 = 0; mt4 < 2; mt4++) {
                        int row = mbase + warp_m + mt4 * 16 + r0l;
                        float* o0 = out + (size_t)row * VOCAB + col;
                        float* o1 = out + (size_t)(row + 8) * VOCAB + col;
                        *(float2*)o0 = make_float2(acc[mt4][nt4][0] + bv0,
                                                   acc[mt4][nt4][1] + bv1);
                        *(float2*)o1 = make_float2(acc[mt4][nt4][2] + bv0,
                                                   acc[mt4][nt4][3] + bv1);
                    }
                }
            }
        }
        lu += 16;
    }
}

// ---------------- finalize -------------------------------------------------------
__global__ void finalize_kernel(float* __restrict__ out) {
    int i = blockIdx.x * blockDim.x + threadIdx.x;
    if (i < 2 * BH) {
        int l = i >> 16;
        int r = i & (BH - 1);
        int b = r >> 10, n = r & 1023;
        unsigned off = hoff_bytes(SEQ, b, n);
        const char* hs = l ? (const char*)g_h1h : (const char*)g_h0h;
        const char* ls = l ? (const char*)g_h1l : (const char*)g_h0l;
        out[(size_t)ROWS * VOCAB + i] =
            __bfloat162float(*(const __nv_bfloat16*)(hs + off)) +
            __bfloat162float(*(const __nv_bfloat16*)(ls + off));
    }
}

// ---------------- launcher --------------------------------------------------------
extern "C" void kernel_launch(void* const* d_in, const int* in_sizes, int n_in,
                              void* d_out, int out_size)
{
    const int*   inputs    = (const int*)  d_in[0];
    const float* hidden    = (const float*)d_in[1];
    const float* embedding = (const float*)d_in[2];
    const float* wx0       = (const float*)d_in[3];
    const float* wh0       = (const float*)d_in[4];
    const float* bh0       = (const float*)d_in[5];
    const float* wx1       = (const float*)d_in[6];
    const float* wh1       = (const float*)d_in[7];
    const float* bh1       = (const float*)d_in[8];
    const float* v_w       = (const float*)d_in[9];
    const float* v_b       = (const float*)d_in[10];
    float* out = (float*)d_out;

    static bool attr_set = false;
    if (!attr_set) {
        cudaFuncSetAttribute(fused_kernel,
                             cudaFuncAttributeMaxDynamicSharedMemorySize,
                             RECUR_SMEM);
        attr_set = true;
    }

    __nv_bfloat16 *dBh, *dBl, *dWh, *dWl, *dXh, *dXl;
    cudaGetSymbolAddress((void**)&dBh, g_Bh);
    cudaGetSymbolAddress((void**)&dBl, g_Bl);
    cudaGetSymbolAddress((void**)&dWh, g_Wh);
    cudaGetSymbolAddress((void**)&dWl, g_Wl);
    cudaGetSymbolAddress((void**)&dXh, g_Xh);
    cudaGetSymbolAddress((void**)&dXl, g_Xl);

    init_kernel<<<(BH + 255) / 256, 256>>>(hidden);
    conv_tiles_kernel<<<(VOCAB * HID / 4 + 255) / 256, 256>>>(
        v_w, 0, dBh, dBl, VOCAB * HID / 4);
    conv_tiles_kernel<<<(HID * HID / 4 + 255) / 256, 256>>>(
        wx0, 0, dWh, dWl, HID * HID / 4);
    conv_tiles_kernel<<<(ROWS * HID / 4 + 255) / 256, 256>>>(
        embedding, inputs, dXh, dXl, ROWS * HID / 4);
    fused_kernel<<<NGRID, NTHR, RECUR_SMEM>>>(wh0, wx1, wh1, bh0, bh1, v_b, out);

    long long need = (long long)ROWS * VOCAB + 2LL * BH;
    if ((long long)out_size >= need) {
        finalize_kernel<<<(2 * BH + 255) / 256, 256>>>(out);
    }
}

// round 16
// speedup vs baseline: 1.0358x; 1.0358x over previous
#include <cuda_runtime.h>
#include <cuda_bf16.h>
#include <math.h>

// Problem constants
#define EMB   1024
#define HID   1024
#define SEQ   128
#define BATCH 64
#define VOCAB 10000
#define VPAD  10112              // 79 * 128
#define BH    (BATCH * HID)      // 65536
#define ROWS  (SEQ * BATCH)      // 8192

// h layout: [slot][16 chunks][8KB swizzled (64 rows x 128B)]
#define H_SLOT_BYTES  131072
#define H_CHUNK_BYTES 8192
// tile layout (B/X/W): [128-row tile][16 chunks][16KB swizzled]
#define T_TILE_BYTES  262144
#define T_CHUNK_BYTES 16384

// Fused persistent kernel config
#define NB_L0 32
#define NBLK  96                 // 32 L0 + 64 L1
#define NGRID 148
#define NT_N  79
#define NTILES (64 * NT_N)       // 5056 logits tiles
#define NXT   512                // 64 x 8 xproj tiles (served first)
#define A_BASE 131072            // recur A stages after weights
#define L0_STAGE 16384
#define L1_STAGE 32768
#define RECUR_SMEM (131072 + 3 * 32768)   // 229376

// 128x128 GEMM config
#define NKT  16
#define OP_BYTES 16384
#define STAGE_BYTES (4 * OP_BYTES)

typedef unsigned long long ull;

// ---------------- scratch (device globals) ----------------------------------
__device__ float g_xproj0[ROWS * HID];
__device__ unsigned g_b0;        // L0 progress: 32 arrivals per step
__device__ unsigned g_b1;        // L1 progress: 64 arrivals per step
__device__ unsigned g_tileq;
__device__ unsigned g_xp[64];    // per-mt xproj tile completion counters
__device__ __nv_bfloat16 g_h0h[(SEQ + 1) * BH];
__device__ __nv_bfloat16 g_h0l[(SEQ + 1) * BH];
__device__ __nv_bfloat16 g_h1h[(SEQ + 1) * BH];
__device__ __nv_bfloat16 g_h1l[(SEQ + 1) * BH];
__device__ __nv_bfloat16 g_Bh[VPAD * HID];
__device__ __nv_bfloat16 g_Bl[VPAD * HID];
__device__ __nv_bfloat16 g_Wh[HID * HID];
__device__ __nv_bfloat16 g_Wl[HID * HID];
__device__ __nv_bfloat16 g_Xh[ROWS * HID];
__device__ __nv_bfloat16 g_Xl[ROWS * HID];

// ---------------- helpers -----------------------------------------------------
__device__ __forceinline__ unsigned smem_u32(const void* p) {
    unsigned a;
    asm("{ .reg .u64 t; cvta.to.shared.u64 t, %1; cvt.u32.u64 %0, t; }"
        : "=r"(a) : "l"(p));
    return a;
}

#define SWZ(o) ((o) ^ (((o) >> 3) & 0x70))

__device__ __forceinline__ unsigned hoff_bytes(int slot, int m, int k) {
    unsigned o = (unsigned)(m * 128 + (k & 63) * 2);
    return (unsigned)(slot * H_SLOT_BYTES + ((k >> 6) * H_CHUNK_BYTES)) + SWZ(o);
}

#define MBAR_INIT(addr, cnt) \
    asm volatile("mbarrier.init.shared.b64 [%0], %1;" \
                 :: "r"((unsigned)(addr)), "r"((unsigned)(cnt)) : "memory")
#define MBAR_EXPECT_TX(addr, tx) \
    asm volatile("mbarrier.arrive.expect_tx.shared.b64 _, [%0], %1;" \
                 :: "r"((unsigned)(addr)), "r"((unsigned)(tx)) : "memory")
#define MBAR_ARRIVE(addr) \
    asm volatile("mbarrier.arrive.shared.b64 _, [%0];" \
                 :: "r"((unsigned)(addr)) : "memory")
#define BAR_SYNC(id, n) \
    asm volatile("bar.sync %0, %1;" :: "r"(id), "r"(n) : "memory")

#define MBARRIER_WAIT_PARITY(addr, par) do {                                  \
    unsigned _m = (unsigned)(addr), _p = (unsigned)(par), _d;                 \
    asm volatile("{\n\t.reg .pred p;\n\t"                                     \
        "mbarrier.try_wait.parity.acquire.cta.shared::cta.b64 p, [%1], %2;\n\t" \
        "selp.b32 %0, 1, 0, p;\n\t}"                                          \
        : "=r"(_d) : "r"(_m), "r"(_p) : "memory");                            \
    if (!_d) {                                                                \
        asm volatile("{\n\t.reg .pred P1;\n\t"                                \
            "WL_%=:\n\t"                                                      \
            "mbarrier.try_wait.parity.acquire.cta.shared::cta.b64 P1, [%0], %1, 0x989680;\n\t" \
            "@P1 bra.uni WD_%=;\n\t"                                          \
            "bra.uni WL_%=;\n\t"                                              \
            "WD_%=:\n\t}" :: "r"(_m), "r"(_p) : "memory");                    \
    }                                                                         \
} while (0)

__device__ __forceinline__ void bulk_g2s(unsigned dst, const void* src,
                                         unsigned bytes, unsigned mbar) {
    asm volatile(
        "cp.async.bulk.shared::cluster.global.mbarrier::complete_tx::bytes "
        "[%0], [%1], %2, [%3];"
        :: "r"(dst), "l"(src), "r"(bytes), "r"(mbar) : "memory");
}

__device__ __forceinline__ unsigned ld_acq(const unsigned* p) {
    unsigned v;
    asm volatile("ld.global.acquire.gpu.b32 %0, [%1];" : "=r"(v) : "l"(p) : "memory");
    return v;
}
__device__ __forceinline__ void red_rel(unsigned* p, unsigned v) {
    asm volatile("red.release.gpu.global.add.u32 [%0], %1;" :: "l"(p), "r"(v) : "memory");
}

__device__ __forceinline__ void ldsm4(unsigned* r, unsigned addr) {
    asm volatile("ldmatrix.sync.aligned.m8n8.x4.shared.b16 {%0,%1,%2,%3}, [%4];"
                 : "=r"(r[0]), "=r"(r[1]), "=r"(r[2]), "=r"(r[3]) : "r"(addr));
}
__device__ __forceinline__ void mma16816(float* c, const unsigned* a,
                                         unsigned b0, unsigned b1) {
    asm volatile(
        "mma.sync.aligned.m16n8k16.row.col.f32.bf16.bf16.f32 "
        "{%0,%1,%2,%3}, {%4,%5,%6,%7}, {%8,%9}, {%0,%1,%2,%3};"
        : "+f"(c[0]), "+f"(c[1]), "+f"(c[2]), "+f"(c[3])
        : "r"(a[0]), "r"(a[1]), "r"(a[2]), "r"(a[3]), "r"(b0), "r"(b1));
}

__device__ __forceinline__ void split_bf16(float v, __nv_bfloat16& h,
                                           __nv_bfloat16& l) {
    h = __float2bfloat16(v);
    l = __float2bfloat16(v - __bfloat162float(h));
}

// ---------------- init ----------------------------------------------------------
__global__ void init_kernel(const float* __restrict__ hidden) {
    int i = blockIdx.x * blockDim.x + threadIdx.x;
    if (i == 0) { g_b0 = 0; g_b1 = 0; g_tileq = 0; }
    if (i < 64) g_xp[i] = 0;
    if (i < BH) {
        int b = i >> 10, n = i & 1023;
        unsigned off = hoff_bytes(0, b, n);
        __nv_bfloat16 h, l;
        split_bf16(hidden[i], h, l);
        *(__nv_bfloat16*)((char*)g_h0h + off) = h;
        *(__nv_bfloat16*)((char*)g_h0l + off) = l;
        split_bf16(hidden[BH + i], h, l);
        *(__nv_bfloat16*)((char*)g_h1h + off) = h;
        *(__nv_bfloat16*)((char*)g_h1l + off) = l;
    }
}

// ---------------- convert fp32 rows -> split bf16 tiles (swizzled) -------------
__global__ __launch_bounds__(256) void conv_tiles_kernel(
    const float* __restrict__ src, const int* __restrict__ idx,
    __nv_bfloat16* __restrict__ dh, __nv_bfloat16* __restrict__ dl, int total4)
{
    int i = blockIdx.x * 256 + threadIdx.x;
    if (i >= total4) return;
    int e = i * 4;
    int r = e >> 10, k = e & 1023;
    int srow = idx ? idx[r] : r;
    float4 a = *(const float4*)(src + (size_t)srow * 1024 + k);
    __nv_bfloat16 h0, l0, h1, l1, h2, l2, h3, l3;
    split_bf16(a.x, h0, l0); split_bf16(a.y, h1, l1);
    split_bf16(a.z, h2, l2); split_bf16(a.w, h3, l3);
    unsigned o = (unsigned)((r & 127) * 128 + (k & 63) * 2);
    unsigned off = (unsigned)((r >> 7) * T_TILE_BYTES + (k >> 6) * T_CHUNK_BYTES)
                 + SWZ(o);
    *(__nv_bfloat162*)((char*)dh + off)     = __nv_bfloat162(h0, h1);
    *(__nv_bfloat162*)((char*)dh + off + 4) = __nv_bfloat162(h2, h3);
    *(__nv_bfloat162*)((char*)dl + off)     = __nv_bfloat162(l0, l1);
    *(__nv_bfloat162*)((char*)dl + off + 4) = __nv_bfloat162(l2, l3);
}

// ---------------- recur: layer-0 step (round-13 structure + xproj gate) --------
__device__ __forceinline__ void step_l0(unsigned sb, unsigned mbf, unsigned mbe,
                                        int bid, int k, int u0, int tid,
                                        int lane, int wid)
{
    const char* a0h = (const char*)g_h0h + (size_t)k * H_SLOT_BYTES;
    const char* a0l = (const char*)g_h0l + (size_t)k * H_SLOT_BYTES;

    if (tid == 256) {
        #pragma unroll 1
        for (int c = 0; c < 16; c++) {
            int uu = u0 + c, s = uu & 3, q = uu >> 2;
            if (uu >= 4) MBARRIER_WAIT_PARITY(mbe + s * 8, (q - 1) & 1);
            unsigned dst = sb + A_BASE + s * L0_STAGE;
            MBAR_EXPECT_TX(mbf + s * 8, 16384u);
            bulk_g2s(dst,        a0h + c * H_CHUNK_BYTES, 8192, mbf + s * 8);
            bulk_g2s(dst + 8192, a0l + c * H_CHUNK_BYTES, 8192, mbf + s * 8);
        }
    } else if (wid < 8) {
        const int wm = wid >> 1, wn = wid & 1;
        const unsigned xm    = (unsigned)((lane & 7) << 4);
        const unsigned aoffA = (unsigned)((wm * 16 + (lane & 7) + ((lane >> 3) & 1) * 8) * 128);
        const unsigned kbA   = (unsigned)((lane >> 4) * 16);
        const unsigned boffB = (unsigned)((wn * 16 + (lane & 7) + ((lane >> 4) << 3)) * 128);
        const unsigned kbB   = (unsigned)(((lane >> 3) & 1) * 16);

        float acc[2][4] = {};

        #pragma unroll 1
        for (int c = 0; c < 16; c++) {
            int uu = u0 + c, s = uu & 3, q = uu >> 2;
            MBARRIER_WAIT_PARITY(mbf + s * 8, q & 1);
            unsigned stg = sb + A_BASE + s * L0_STAGE;
            unsigned wbh = sb + (unsigned)(c * 4096);
            unsigned wbl = wbh + 65536;
            #pragma unroll
            for (int ks = 0; ks < 4; ks++) {
                unsigned kA = ((unsigned)(ks * 32) + kbA) ^ xm;
                unsigned kB = ((unsigned)(ks * 32) + kbB) ^ xm;
                unsigned ah[4], al[4], bh[4], bl[4];
                ldsm4(ah, stg + aoffA + kA);
                ldsm4(al, stg + 8192 + aoffA + kA);
                ldsm4(bh, wbh + boffB + kB);
                ldsm4(bl, wbl + boffB + kB);
                mma16816(acc[0], ah, bh[0], bh[1]);
                mma16816(acc[0], al, bh[0], bh[1]);
                mma16816(acc[0], ah, bl[0], bl[1]);
                mma16816(acc[1], ah, bh[2], bh[3]);
                mma16816(acc[1], al, bh[2], bh[3]);
                mma16816(acc[1], ah, bl[2], bl[3]);
            }
            if (lane == 0) MBAR_ARRIVE(mbe + s * 8);
        }

        // gate on xproj tiles covering rows of this step
        int mt = k >> 1;
        while (ld_acq(&g_xp[mt]) < 8u) { }

        int r = lane >> 2, c0 = 2 * (lane & 3);
        int mrow = wm * 16 + r;
        #pragma unroll
        for (int n2 = 0; n2 < 2; n2++) {
            int gn = bid * 32 + wn * 16 + n2 * 8 + c0;
            const float* xp0 = g_xproj0 + ((size_t)k * BATCH + mrow) * HID + gn;
            const float* xp1 = g_xproj0 + ((size_t)k * BATCH + mrow + 8) * HID + gn;
            float2 x0 = *(const float2*)xp0;
            float2 x1 = *(const float2*)xp1;
            float t0 = tanhf(acc[n2][0] + x0.x);
            float t1 = tanhf(acc[n2][1] + x0.y);
            float t2 = tanhf(acc[n2][2] + x1.x);
            float t3 = tanhf(acc[n2][3] + x1.y);
            __nv_bfloat16 h0, l0, h1, l1, h2, l2, h3, l3;
            split_bf16(t0, h0, l0); split_bf16(t1, h1, l1);
            split_bf16(t2, h2, l2); split_bf16(t3, h3, l3);
            unsigned o0 = hoff_bytes(k + 1, mrow, gn);
            unsigned o1 = hoff_bytes(k + 1, mrow + 8, gn);
            *(__nv_bfloat162*)((char*)g_h0h + o0) = __nv_bfloat162(h0, h1);
            *(__nv_bfloat162*)((char*)g_h0l + o0) = __nv_bfloat162(l0, l1);
            *(__nv_bfloat162*)((char*)g_h0h + o1) = __nv_bfloat162(h2, h3);
            *(__nv_bfloat162*)((char*)g_h0l + o1) = __nv_bfloat162(l2, l3);
        }
    }
}

// ---------------- recur: layer-1 step (round-13 structure) ---------------------
__device__ __forceinline__ void step_l1(char* smc, unsigned sb, unsigned mbf,
                                        unsigned mbe, int bid, int k, int u0,
                                        int tid, int lane, int wid,
                                        const float* __restrict__ bh1)
{
    const char* a0h = (const char*)g_h0h + (size_t)k * H_SLOT_BYTES;
    const char* a0l = (const char*)g_h0l + (size_t)k * H_SLOT_BYTES;
    const char* a1h = (const char*)g_h1h + (size_t)(k - 1) * H_SLOT_BYTES;
    const char* a1l = (const char*)g_h1l + (size_t)(k - 1) * H_SLOT_BYTES;

    if (tid == 256) {
        #pragma unroll 1
        for (int c = 0; c < 16; c++) {
            int uu = u0 + c, s = uu % 3, q = uu / 3;
            if (uu >= 3) MBARRIER_WAIT_PARITY(mbe + s * 8, (q - 1) & 1);
            unsigned dst = sb + A_BASE + s * L1_STAGE;
            MBAR_EXPECT_TX(mbf + s * 8, 32768u);
            bulk_g2s(dst,         a0h + c * H_CHUNK_BYTES, 8192, mbf + s * 8);
            bulk_g2s(dst + 8192,  a0l + c * H_CHUNK_BYTES, 8192, mbf + s * 8);
            bulk_g2s(dst + 16384, a1h + c * H_CHUNK_BYTES, 8192, mbf + s * 8);
            bulk_g2s(dst + 24576, a1l + c * H_CHUNK_BYTES, 8192, mbf + s * 8);
        }
    } else if (wid < 8) {
        const int wm = wid >> 1, kq = wid & 1;
        const unsigned xm    = (unsigned)((lane & 7) << 4);
        const unsigned aoffA = (unsigned)((wm * 16 + (lane & 7) + ((lane >> 3) & 1) * 8) * 128);
        const unsigned kbA   = (unsigned)((lane >> 4) * 16);
        const unsigned boffB = (unsigned)(((lane & 7) + ((lane >> 4) << 3)) * 128);
        const unsigned kbB   = (unsigned)(((lane >> 3) & 1) * 16);
        const unsigned aq    = (unsigned)(kq * 16384);

        float acc[2][4] = {};

        #pragma unroll 1
        for (int c = 0; c < 16; c++) {
            int uu = u0 + c, s = uu % 3, q = uu / 3;
            MBARRIER_WAIT_PARITY(mbf + s * 8, q & 1);
            unsigned stg = sb + A_BASE + s * L1_STAGE + aq;
            unsigned wbh = sb + (unsigned)(kq * 65536 + c * 2048);
            unsigned wbl = wbh + 32768;
            #pragma unroll
            for (int ks = 0; ks < 4; ks++) {
                unsigned kA = ((unsigned)(ks * 32) + kbA) ^ xm;
                unsigned kB = ((unsigned)(ks * 32) + kbB) ^ xm;
                unsigned ah[4], al[4], bh[4], bl[4];
                ldsm4(ah, stg + aoffA + kA);
                ldsm4(al, stg + 8192 + aoffA + kA);
                ldsm4(bh, wbh + boffB + kB);
                ldsm4(bl, wbl + boffB + kB);
                mma16816(acc[0], ah, bh[0], bh[1]);
                mma16816(acc[0], al, bh[0], bh[1]);
                mma16816(acc[0], ah, bl[0], bl[1]);
                mma16816(acc[1], ah, bh[2], bh[3]);
                mma16816(acc[1], al, bh[2], bh[3]);
                mma16816(acc[1], ah, bl[2], bl[3]);
            }
            if (lane == 0) MBAR_ARRIVE(mbe + s * 8);
        }

        float* red = (float*)(smc + A_BASE + ((u0 + 15) % 3) * L1_STAGE);
        int r = lane >> 2, c0 = 2 * (lane & 3);
        int mrow = wm * 16 + r;
        BAR_SYNC(1, 256);
        if (kq == 1) {
            #pragma unroll
            for (int n2 = 0; n2 < 2; n2++) {
                int col = n2 * 8 + c0;
                *(float2*)&red[mrow * 16 + col]       = make_float2(acc[n2][0], acc[n2][1]);
                *(float2*)&red[(mrow + 8) * 16 + col] = make_float2(acc[n2][2], acc[n2][3]);
            }
        }
        BAR_SYNC(1, 256);
        if (kq == 0) {
            int gnb = (bid - NB_L0) * 16;
            #pragma unroll
            for (int n2 = 0; n2 < 2; n2++) {
                int col = n2 * 8 + c0;
                int gn = gnb + col;
                float2 r0 = *(const float2*)&red[mrow * 16 + col];
                float2 r1 = *(const float2*)&red[(mrow + 8) * 16 + col];
                float2 bv = *(const float2*)(bh1 + gn);
                float t0 = tanhf(acc[n2][0] + r0.x + bv.x);
                float t1 = tanhf(acc[n2][1] + r0.y + bv.y);
                float t2 = tanhf(acc[n2][2] + r1.x + bv.x);
                float t3 = tanhf(acc[n2][3] + r1.y + bv.y);
                __nv_bfloat16 h0, l0, h1, l1, h2, l2, h3, l3;
                split_bf16(t0, h0, l0); split_bf16(t1, h1, l1);
                split_bf16(t2, h2, l2); split_bf16(t3, h3, l3);
                unsigned o0 = hoff_bytes(k, mrow, gn);
                unsigned o1 = hoff_bytes(k, mrow + 8, gn);
                *(__nv_bfloat162*)((char*)g_h1h + o0) = __nv_bfloat162(h0, h1);
                *(__nv_bfloat162*)((char*)g_h1l + o0) = __nv_bfloat162(l0, l1);
                *(__nv_bfloat162*)((char*)g_h1h + o1) = __nv_bfloat162(h2, h3);
                *(__nv_bfloat162*)((char*)g_h1l + o1) = __nv_bfloat162(l2, l3);
            }
        }
    }
}

// ---------------- shared 128x128 GEMM machinery --------------------------------
template<bool FOURTH>
__device__ __forceinline__ void compute_chunk128(
    unsigned st, const unsigned* aoffA, const unsigned* aoffB,
    unsigned kbA, unsigned kbB, unsigned xm, float acc[4][4][4])
{
    #pragma unroll
    for (int ks = 0; ks < 4; ks++) {
        unsigned kA = ((unsigned)(ks * 32) + kbA) ^ xm;
        unsigned kB = ((unsigned)(ks * 32) + kbB) ^ xm;
        unsigned ah[4][4], al[4][4], bh[2][4], bl[2][4];
        #pragma unroll
        for (int mt = 0; mt < 4; mt++) {
            ldsm4(ah[mt], st + 0 * OP_BYTES + aoffA[mt] + kA);
            ldsm4(al[mt], st + 1 * OP_BYTES + aoffA[mt] + kA);
        }
        #pragma unroll
        for (int nt = 0; nt < 2; nt++) {
            ldsm4(bh[nt], st + 2 * OP_BYTES + aoffB[nt] + kB);
            ldsm4(bl[nt], st + 3 * OP_BYTES + aoffB[nt] + kB);
        }
        #pragma unroll
        for (int mt = 0; mt < 4; mt++) {
            #pragma unroll
            for (int n2 = 0; n2 < 2; n2++) {
                mma16816(acc[mt][n2 * 2],     ah[mt], bh[n2][0], bh[n2][1]);
                mma16816(acc[mt][n2 * 2],     al[mt], bh[n2][0], bh[n2][1]);
                mma16816(acc[mt][n2 * 2],     ah[mt], bl[n2][0], bl[n2][1]);
                if (FOURTH)
                    mma16816(acc[mt][n2 * 2], al[mt], bl[n2][0], bl[n2][1]);
                mma16816(acc[mt][n2 * 2 + 1], ah[mt], bh[n2][2], bh[n2][3]);
                mma16816(acc[mt][n2 * 2 + 1], al[mt], bh[n2][2], bh[n2][3]);
                mma16816(acc[mt][n2 * 2 + 1], ah[mt], bl[n2][2], bl[n2][3]);
                if (FOURTH)
                    mma16816(acc[mt][n2 * 2 + 1], al[mt], bl[n2][2], bl[n2][3]);
            }
        }
    }
}

__device__ __forceinline__ void tile_geometry(int lane, int wid,
                                              unsigned* aoffA, unsigned* aoffB,
                                              unsigned& kbA, unsigned& kbB,
                                              unsigned& xm)
{
    const int warp_m = (wid >> 2) * 64;
    const int warp_n = (wid & 3) * 32;
    xm  = (unsigned)((lane & 7) << 4);
    const int rowA = (lane & 7) + ((lane >> 3) & 1) * 8;
    kbA = (unsigned)((lane >> 4) * 16);
    const int rowB = (lane & 7) + ((lane >> 4) << 3);
    kbB = (unsigned)(((lane >> 3) & 1) * 16);
    #pragma unroll
    for (int mt = 0; mt < 4; mt++)
        aoffA[mt] = (unsigned)((warp_m + mt * 16 + rowA) * 128);
    #pragma unroll
    for (int nt = 0; nt < 2; nt++)
        aoffB[nt] = (unsigned)((warp_n + nt * 16 + rowB) * 128);
}

// ---------------- fused persistent kernel --------------------------------------
__global__ __launch_bounds__(288, 1) void fused_kernel(
    const float* __restrict__ wh0, const float* __restrict__ wx1,
    const float* __restrict__ wh1, const float* __restrict__ bh0,
    const float* __restrict__ bh1, const float* __restrict__ vb,
    float* __restrict__ out)
{
    extern __shared__ char sm[];
    __shared__ ull s_full[4], s_empty[4];   // recur rings
    __shared__ ull s_lf[2], s_le[2];        // worker rings
    __shared__ int s_tile;
    const int tid = threadIdx.x;
    const int lane = tid & 31, wid = tid >> 5;
    const int bid = blockIdx.x;
    const unsigned sb = smem_u32(sm);
    const unsigned mbf = smem_u32(&s_full[0]);
    const unsigned mbe = smem_u32(&s_empty[0]);
    const unsigned mlf = smem_u32(&s_lf[0]);
    const unsigned mle = smem_u32(&s_le[0]);

    if (tid == 0) {
        #pragma unroll
        for (int s = 0; s < 4; s++) {
            MBAR_INIT(mbf + s * 8, 1);
            MBAR_INIT(mbe + s * 8, 8);
        }
        #pragma unroll
        for (int s = 0; s < 2; s++) {
            MBAR_INIT(mlf + s * 8, 1);
            MBAR_INIT(mle + s * 8, 8);
        }
    }
    __syncthreads();

    // ================= recurrence phase (blocks 0..95) =================
    if (bid < NBLK) {
        const bool is_l1 = (bid >= NB_L0);
        if (!is_l1) {
            int nb = bid * 32;
            for (int idx = tid; idx < 32 * 1024; idx += 288) {
                int n = idx >> 10, kk = idx & 1023;
                float w = wh0[(size_t)(nb + n) * HID + kk];
                __nv_bfloat16 h, l; split_bf16(w, h, l);
                int c = kk >> 6;
                unsigned off = SWZ((unsigned)(n * 128 + (kk & 63) * 2));
                *(__nv_bfloat16*)(sm + c * 4096 + off) = h;
                *(__nv_bfloat16*)(sm + 65536 + c * 4096 + off) = l;
            }
        } else {
            int nb = (bid - NB_L0) * 16;
            for (int idx = tid; idx < 2 * 16 * 1024; idx += 288) {
                int mat = idx >> 14;
                int rr = idx & 16383;
                int n = rr >> 10, kk = rr & 1023;
                const float* W = mat ? wh1 : wx1;
                float w = W[(size_t)(nb + n) * HID + kk];
                __nv_bfloat16 h, l; split_bf16(w, h, l);
                int c = kk >> 6;
                unsigned off = SWZ((unsigned)(n * 128 + (kk & 63) * 2));
                char* base = sm + mat * 65536;
                *(__nv_bfloat16*)(base + c * 2048 + off) = h;
                *(__nv_bfloat16*)(base + 32768 + c * 2048 + off) = l;
            }
        }
        __syncthreads();

        if (!is_l1) {
            // -------- L0: free-running chain gated only on g_b0 --------
            int u = 0;
            for (int k = 0; k < SEQ; k++) {
                if (k > 0) {
                    if (tid == 0) {
                        unsigned need = (unsigned)k * 32u;
                        while (ld_acq(&g_b0) < need) { }
                    }
                    __syncthreads();
                }
                step_l0(sb, mbf, mbe, bid, k, u, tid, lane, wid);
                u += 16;
                __syncthreads();
                if (tid == 0) red_rel(&g_b0, 1u);
            }
        } else {
            // -------- L1: gated on g_b0 (h0[k]) and g_b1 (h1[k-1]) --------
            int u = 0;
            for (int k = 1; k <= SEQ; k++) {
                if (tid == 0) {
                    unsigned need0 = (unsigned)k * 32u;
                    while (ld_acq(&g_b0) < need0) { }
                    if (k >= 2) {
                        unsigned need1 = (unsigned)(k - 1) * 64u;
                        while (ld_acq(&g_b1) < need1) { }
                    }
                }
                __syncthreads();
                step_l1(sm, sb, mbf, mbe, bid, k, u, tid, lane, wid, bh1);
                u += 16;
                __syncthreads();
                if (tid == 0) red_rel(&g_b1, 1u);
            }
        }
    }

    // ================= tile phase: xproj (t<NXT) then logits =================
    const char* ahb = (const char*)g_h1h;
    const char* alb = (const char*)g_h1l;
    int lu = 0;
    int prev_mt = -1;

    while (true) {
        __syncthreads();
        if (tid == 0) {
            if (prev_mt >= 0) {
                red_rel(&g_xp[prev_mt], 1u);
                prev_mt = -1;
            }
            unsigned t = atomicAdd(&g_tileq, 1u);
            s_tile = (int)t;
            if (t < NXT) {
                prev_mt = (int)(t >> 3);
            } else if (t < NXT + NTILES) {
                // h1 slots mt*2+1, mt*2+2 => L1 steps through mt*2+2
                unsigned need = (unsigned)(((t - NXT) / NT_N) * 2 + 2) * 64u;
                while (ld_acq(&g_b1) < need) { }
            }
        }
        __syncthreads();
        int t = s_tile;
        if (t >= NXT + NTILES) break;

        if (t < NXT) {
            // -------- xproj tile: 4-product, A=gathered emb, B=wx0 --------
            int mt = t >> 3, nt = t & 7;
            int mbase = mt * 128, nbase = nt * 128;
            const char* xah = (const char*)g_Xh + (size_t)mt * T_TILE_BYTES;
            const char* xal = (const char*)g_Xl + (size_t)mt * T_TILE_BYTES;
            const char* xbh = (const char*)g_Wh + (size_t)nt * T_TILE_BYTES;
            const char* xbl = (const char*)g_Wl + (size_t)nt * T_TILE_BYTES;

            if (tid == 256) {
                #pragma unroll 1
                for (int c = 0; c < NKT; c++) {
                    int uu = lu + c, s = uu & 1, q = uu >> 1;
                    if (uu >= 2) MBARRIER_WAIT_PARITY(mle + s * 8, (q - 1) & 1);
                    unsigned dst = sb + (unsigned)(s * STAGE_BYTES);
                    MBAR_EXPECT_TX(mlf + s * 8, 65536u);
                    bulk_g2s(dst,                xah + c * T_CHUNK_BYTES, 16384, mlf + s * 8);
                    bulk_g2s(dst + OP_BYTES,     xal + c * T_CHUNK_BYTES, 16384, mlf + s * 8);
                    bulk_g2s(dst + 2 * OP_BYTES, xbh + c * T_CHUNK_BYTES, 16384, mlf + s * 8);
                    bulk_g2s(dst + 3 * OP_BYTES, xbl + c * T_CHUNK_BYTES, 16384, mlf + s * 8);
                }
            } else if (wid < 8) {
                unsigned aoffA[4], aoffB[2], kbA, kbB, xm;
                tile_geometry(lane, wid, aoffA, aoffB, kbA, kbB, xm);
                float acc[4][4][4] = {};
                #pragma unroll 1
                for (int c = 0; c < NKT; c++) {
                    int uu = lu + c, s = uu & 1, q = uu >> 1;
                    MBARRIER_WAIT_PARITY(mlf + s * 8, q & 1);
                    compute_chunk128<true>(sb + (unsigned)(s * STAGE_BYTES),
                                           aoffA, aoffB, kbA, kbB, xm, acc);
                    if (lane == 0) MBAR_ARRIVE(mle + s * 8);
                }
                const int warp_m = (wid >> 2) * 64;
                const int warp_n = (wid & 3) * 32;
                const int r0l = lane >> 2;
                const int c0l = 2 * (lane & 3);
                #pragma unroll
                for (int nt4 = 0; nt4 < 4; nt4++) {
                    int col = nbase + warp_n + nt4 * 8 + c0l;
                    float2 bv = *(const float2*)(bh0 + col);
                    #pragma unroll
                    for (int mt4 = 0; mt4 < 4; mt4++) {
                        int row = mbase + warp_m + mt4 * 16 + r0l;
                        float* o0 = g_xproj0 + (size_t)row * HID + col;
                        float* o1 = g_xproj0 + (size_t)(row + 8) * HID + col;
                        *(float2*)o0 = make_float2(acc[mt4][nt4][0] + bv.x,
                                                   acc[mt4][nt4][1] + bv.y);
                        *(float2*)o1 = make_float2(acc[mt4][nt4][2] + bv.x,
                                                   acc[mt4][nt4][3] + bv.y);
                    }
                }
            }
        } else {
            // -------- logits tile: 3-product, A=h1 slots, B=v_w --------
            int tl = t - NXT;
            int mt = tl / NT_N, nt = tl - mt * NT_N;
            int mbase = mt * 128, nbase = nt * 128;
            int s0 = mt * 2 + 1;
            const char* bhb = (const char*)g_Bh + (size_t)nt * T_TILE_BYTES;
            const char* blb = (const char*)g_Bl + (size_t)nt * T_TILE_BYTES;

            if (tid == 256) {
                #pragma unroll 1
                for (int c = 0; c < NKT; c++) {
                    int uu = lu + c, s = uu & 1, q = uu >> 1;
                    if (uu >= 2) MBARRIER_WAIT_PARITY(mle + s * 8, (q - 1) & 1);
                    unsigned dst = sb + (unsigned)(s * STAGE_BYTES);
                    MBAR_EXPECT_TX(mlf + s * 8, 65536u);
                    bulk_g2s(dst,                   ahb + (size_t)s0 * H_SLOT_BYTES + c * H_CHUNK_BYTES, 8192, mlf + s * 8);
                    bulk_g2s(dst + 8192,            ahb + (size_t)(s0 + 1) * H_SLOT_BYTES + c * H_CHUNK_BYTES, 8192, mlf + s * 8);
                    bulk_g2s(dst + OP_BYTES,        alb + (size_t)s0 * H_SLOT_BYTES + c * H_CHUNK_BYTES, 8192, mlf + s * 8);
                    bulk_g2s(dst + OP_BYTES + 8192, alb + (size_t)(s0 + 1) * H_SLOT_BYTES + c * H_CHUNK_BYTES, 8192, mlf + s * 8);
                    bulk_g2s(dst + 2 * OP_BYTES,    bhb + c * T_CHUNK_BYTES, 16384, mlf + s * 8);
                    bulk_g2s(dst + 3 * OP_BYTES,    blb + c * T_CHUNK_BYTES, 16384, mlf + s * 8);
                }
            } else if (wid < 8) {
                unsigned aoffA[4], aoffB[2], kbA, kbB, xm;
                tile_geometry(lane, wid, aoffA, aoffB, kbA, kbB, xm);
                float acc[4][4][4] = {};
                #pragma unroll 1
                for (int c = 0; c < NKT; c++) {
                    int uu = lu + c, s = uu & 1, q = uu >> 1;
                    MBARRIER_WAIT_PARITY(mlf + s * 8, q & 1);
                    compute_chunk128<false>(sb + (unsigned)(s * STAGE_BYTES),
                                            aoffA, aoffB, kbA, kbB, xm, acc);
                    if (lane == 0) MBAR_ARRIVE(mle + s * 8);
                }
                const int warp_m = (wid >> 2) * 64;
                const int warp_n = (wid & 3) * 32;
                const int r0l = lane >> 2;
                const int c0l = 2 * (lane & 3);
                #pragma unroll
                for (int nt4 = 0; nt4 < 4; nt4++) {
                    int col = nbase + warp_n + nt4 * 8 + c0l;
                    if (col >= VOCAB) continue;
                    float bv0 = vb[col], bv1 = vb[col + 1];
                    #pragma unroll
                    for (int mt4 = 0; mt4 < 4; mt4++) {
                        int row = mbase + warp_m + mt4 * 16 + r0l;
                        float* o0 = out + (size_t)row * VOCAB + col;
                        float* o1 = out + (size_t)(row + 8) * VOCAB + col;
                        *(float2*)o0 = make_float2(acc[mt4][nt4][0] + bv0,
                                                   acc[mt4][nt4][1] + bv1);
                        *(float2*)o1 = make_float2(acc[mt4][nt4][2] + bv0,
                                                   acc[mt4][nt4][3] + bv1);
                    }
                }
            }
        }
        lu += 16;
    }
}

// ---------------- finalize -------------------------------------------------------
__global__ void finalize_kernel(float* __restrict__ out) {
    int i = blockIdx.x * blockDim.x + threadIdx.x;
    if (i < 2 * BH) {
        int l = i >> 16;
        int r = i & (BH - 1);
        int b = r >> 10, n = r & 1023;
        unsigned off = hoff_bytes(SEQ, b, n);
        const char* hs = l ? (const char*)g_h1h : (const char*)g_h0h;
        const char* ls = l ? (const char*)g_h1l : (const char*)g_h0l;
        out[(size_t)ROWS * VOCAB + i] =
            __bfloat162float(*(const __nv_bfloat16*)(hs + off)) +
            __bfloat162float(*(const __nv_bfloat16*)(ls + off));
    }
}

// ---------------- launcher --------------------------------------------------------
extern "C" void kernel_launch(void* const* d_in, const int* in_sizes, int n_in,
                              void* d_out, int out_size)
{
    const int*   inputs    = (const int*)  d_in[0];
    const float* hidden    = (const float*)d_in[1];
    const float* embedding = (const float*)d_in[2];
    const float* wx0       = (const float*)d_in[3];
    const float* wh0       = (const float*)d_in[4];
    const float* bh0       = (const float*)d_in[5];
    const float* wx1       = (const float*)d_in[6];
    const float* wh1       = (const float*)d_in[7];
    const float* bh1       = (const float*)d_in[8];
    const float* v_w       = (const float*)d_in[9];
    const float* v_b       = (const float*)d_in[10];
    float* out = (float*)d_out;

    static bool attr_set = false;
    if (!attr_set) {
        cudaFuncSetAttribute(fused_kernel,
                             cudaFuncAttributeMaxDynamicSharedMemorySize,
                             RECUR_SMEM);
        attr_set = true;
    }

    __nv_bfloat16 *dBh, *dBl, *dWh, *dWl, *dXh, *dXl;
    cudaGetSymbolAddress((void**)&dBh, g_Bh);
    cudaGetSymbolAddress((void**)&dBl, g_Bl);
    cudaGetSymbolAddress((void**)&dWh, g_Wh);
    cudaGetSymbolAddress((void**)&dWl, g_Wl);
    cudaGetSymbolAddress((void**)&dXh, g_Xh);
    cudaGetSymbolAddress((void**)&dXl, g_Xl);

    init_kernel<<<(BH + 255) / 256, 256>>>(hidden);
    conv_tiles_kernel<<<(VOCAB * HID / 4 + 255) / 256, 256>>>(
        v_w, 0, dBh, dBl, VOCAB * HID / 4);
    conv_tiles_kernel<<<(HID * HID / 4 + 255) / 256, 256>>>(
        wx0, 0, dWh, dWl, HID * HID / 4);
    conv_tiles_kernel<<<(ROWS * HID / 4 + 255) / 256, 256>>>(
        embedding, inputs, dXh, dXl, ROWS * HID / 4);
    fused_kernel<<<NGRID, 288, RECUR_SMEM>>>(wh0, wx1, wh1, bh0, bh1, v_b, out);

    long long need = (long long)ROWS * VOCAB + 2LL * BH;
    if ((long long)out_size >= need) {
        finalize_kernel<<<(2 * BH + 255) / 256, 256>>>(out);
    }
}